// round 12
// baseline (speedup 1.0000x reference)
#include <cuda_runtime.h>
#include <math.h>
#include <stdint.h>

#define NN 50000
#define NE 800000
#define MUL 32
#define AA 8
#define VE 4
#define FCI 16
#define FCH 64
#define W_NUMEL 128

// ---------- scratch (device-code-only symbols; never passed from host) ----------
__device__ __align__(16) float g_x[NN * MUL];     // lin1 output
__device__ __align__(16) float g_sc[NN * MUL];    // self-connection output
__device__ __align__(16) float g_agg[NN * MUL];   // scatter-add accumulator
__device__ __align__(16) float g_nf[NN * MUL];    // node features between layers
__device__ __align__(16) float g_ea[NE * VE];     // edge attrs between layers
// lane-major pre-built tf32 B-fragments of W1^T: [(ng*8+k8)*4+nt][lane] -> (b0,b1)
__device__ __align__(16) uint2 g_w1fhi[4 * 8 * 4 * 32];
__device__ __align__(16) uint2 g_w1flo[4 * 8 * 4 * 32];

// ---------------------------------------------------------------
__global__ void zero_agg_kernel() {
    int i = blockIdx.x * blockDim.x + threadIdx.x;
    if (i < NN * MUL) g_agg[i] = 0.0f;
}

// ---------------- MMA helpers ----------------
__device__ __forceinline__ uint32_t f2tf32(float f) {
    uint32_t r;
    asm("cvt.rna.tf32.f32 %0, %1;" : "=r"(r) : "f"(f));
    return r;
}
__device__ __forceinline__ void tf32_split(float f, uint32_t& hi, uint32_t& lo) {
    hi = f2tf32(f);
    float res = f - __uint_as_float(hi);
    lo = f2tf32(res);
}
__device__ __forceinline__ void mma_tf32(float* c, const uint32_t* a, const uint32_t* b) {
    asm volatile(
        "mma.sync.aligned.m16n8k8.row.col.f32.tf32.tf32.f32 "
        "{%0,%1,%2,%3},{%4,%5,%6,%7},{%8,%9},{%0,%1,%2,%3};"
        : "+f"(c[0]), "+f"(c[1]), "+f"(c[2]), "+f"(c[3])
        : "r"(a[0]), "r"(a[1]), "r"(a[2]), "r"(a[3]), "r"(b[0]), "r"(b[1]));
}

// prep: build lane-major tf32 hi/lo B-fragments of W1^T.
// Fragment for lane (g,t) at (ng,k8,nt): n = 32*ng+8*nt+g, k = 8*k8+t,
// value = ( W1T[n][k], W1T[n][k+4] ), W1T[n][j] = fw1[j*128+n].
__global__ void w1_frag_kernel(const float* __restrict__ fw1) {
    int i = blockIdx.x * blockDim.x + threadIdx.x;   // 0 .. 4095
    if (i >= 4 * 8 * 4 * 32) return;
    int lane = i & 31, nt = (i >> 5) & 3, k8 = (i >> 7) & 7, ng = i >> 10;
    int g = lane >> 2, t = lane & 3;
    int n = 32 * ng + 8 * nt + g;
    int k = 8 * k8 + t;
    float f0 = fw1[k * W_NUMEL + n];
    float f1 = fw1[(k + 4) * W_NUMEL + n];
    uint32_t h0, l0, h1, l1;
    tf32_split(f0, h0, l0);
    tf32_split(f1, h1, l1);
    g_w1fhi[i] = make_uint2(h0, h1);
    g_w1flo[i] = make_uint2(l0, l1);
}

// Dual fctp: blocks [0, ng) compute sc_w -> g_sc ; blocks [ng, 2ng) compute lin1_w -> g_x
__global__ __launch_bounds__(256) void fctp_dual_kernel(
    const float* __restrict__ a, const float* __restrict__ b,
    const float* __restrict__ w_sc, const float* __restrict__ w_lin1, int ng)
{
    __shared__ float ws[MUL * AA * MUL];  // 32KB
    int half = (blockIdx.x >= ng) ? 1 : 0;
    const float* w = half ? w_lin1 : w_sc;
    for (int i = threadIdx.x; i < MUL * AA * MUL; i += 256) ws[i] = w[i];
    __syncthreads();

    int blk = half ? (blockIdx.x - ng) : blockIdx.x;
    int n = blk * 256 + threadIdx.x;
    if (n >= NN) return;
    const float* ap = a ? a : g_nf;
    float* out = half ? g_x : g_sc;

    float attr[AA];
#pragma unroll
    for (int v = 0; v < AA; v++) attr[v] = b[n * AA + v];

    float4 acc4[8];
#pragma unroll
    for (int k4 = 0; k4 < 8; k4++) acc4[k4] = make_float4(0.f, 0.f, 0.f, 0.f);

    const float4* arow = (const float4*)(ap + (size_t)n * MUL);
    for (int u4 = 0; u4 < 8; u4++) {
        float4 av = arow[u4];
        float au[4] = {av.x, av.y, av.z, av.w};
#pragma unroll
        for (int uu = 0; uu < 4; uu++) {
            int u = u4 * 4 + uu;
#pragma unroll
            for (int v = 0; v < AA; v++) {
                float p = au[uu] * attr[v];
                const float4* wp = (const float4*)&ws[(u * AA + v) * MUL];
#pragma unroll
                for (int k4 = 0; k4 < 8; k4++) {
                    float4 wv = wp[k4];
                    acc4[k4].x += p * wv.x;
                    acc4[k4].y += p * wv.y;
                    acc4[k4].z += p * wv.z;
                    acc4[k4].w += p * wv.w;
                }
            }
        }
    }
    const float s = 1.0f / 16.0f;
    float4* op = (float4*)(out + (size_t)n * MUL);
#pragma unroll
    for (int k4 = 0; k4 < 8; k4++) {
        float4 o = acc4[k4];
        o.x *= s; o.y *= s; o.z *= s; o.w *= s;
        op[k4] = o;
    }
}

// lin2 + alpha + combine (+ optional sin). out == nullptr -> write g_nf
__global__ __launch_bounds__(256) void node_post_kernel(
    const float* __restrict__ b, const float* __restrict__ lin2w,
    const float* __restrict__ alw, float* __restrict__ out, int apply_sin)
{
    __shared__ float ws[MUL * AA * MUL];  // 32KB
    __shared__ float as[MUL * AA];        // 1KB
    for (int i = threadIdx.x; i < MUL * AA * MUL; i += 256) ws[i] = lin2w[i];
    for (int i = threadIdx.x; i < MUL * AA; i += 256) as[i] = alw[i];
    __syncthreads();

    int n = blockIdx.x * 256 + threadIdx.x;
    if (n >= NN) return;
    float* op = out ? out : g_nf;

    float attr[AA];
#pragma unroll
    for (int v = 0; v < AA; v++) attr[v] = b[n * AA + v];

    float4 acc4[8];
#pragma unroll
    for (int k4 = 0; k4 < 8; k4++) acc4[k4] = make_float4(0.f, 0.f, 0.f, 0.f);
    float aacc = 0.0f;

    const float4* arow = (const float4*)(g_agg + (size_t)n * MUL);
    for (int u4 = 0; u4 < 8; u4++) {
        float4 av = arow[u4];
        float au[4] = {av.x, av.y, av.z, av.w};
#pragma unroll
        for (int uu = 0; uu < 4; uu++) {
            int u = u4 * 4 + uu;
#pragma unroll
            for (int v = 0; v < AA; v++) {
                float p = au[uu] * attr[v];
                aacc += p * as[u * AA + v];
                const float4* wp = (const float4*)&ws[(u * AA + v) * MUL];
#pragma unroll
                for (int k4 = 0; k4 < 8; k4++) {
                    float4 wv = wp[k4];
                    acc4[k4].x += p * wv.x;
                    acc4[k4].y += p * wv.y;
                    acc4[k4].z += p * wv.z;
                    acc4[k4].w += p * wv.w;
                }
            }
        }
    }
    const float s = 1.0f / 16.0f;
    float alpha = aacc * s;
    const float4* scp = (const float4*)(g_sc + (size_t)n * MUL);
    float4* outp = (float4*)(op + (size_t)n * MUL);
#pragma unroll
    for (int k4 = 0; k4 < 8; k4++) {
        float4 sc = scp[k4];
        float4 cv = acc4[k4];
        float4 o;
        o.x = sc.x + alpha * (cv.x * s);
        o.y = sc.y + alpha * (cv.y * s);
        o.z = sc.z + alpha * (cv.z * s);
        o.w = sc.w + alpha * (cv.w * s);
        if (apply_sin) { o.x = sinf(o.x); o.y = sinf(o.y); o.z = sinf(o.z); o.w = sinf(o.w); }
        outp[k4] = o;
    }
}

// 16B-aligned 4-wide global float add (native vector atomic on sm_90+).
__device__ __forceinline__ void red_add_v4(float* ptr, float a, float b, float c, float d)
{
#if defined(__CUDA_ARCH__) && (__CUDA_ARCH__ >= 900) && (CUDART_VERSION >= 12080)
    atomicAdd((float4*)ptr, make_float4(a, b, c, d));
#else
    atomicAdd(ptr + 0, a);
    atomicAdd(ptr + 1, b);
    atomicAdd(ptr + 2, c);
    atomicAdd(ptr + 3, d);
#endif
}

// smem layout (floats) for edge_mma_kernel  (W planes live in global/L1)
#define HS_STRIDE 68
#define XS_STRIDE 36
#define OFF_HS   0
#define OFF_XS   (128 * HS_STRIDE)                 // 8704
#define OFF_W0   (OFF_XS + 128 * XS_STRIDE)        // 13312
#define OFF_SCE  (OFF_W0 + FCI * FCH)              // 14336
#define OFF_EAS  (OFF_SCE + MUL * VE * VE)         // 14848
#define OFF_DSS  (OFF_EAS + 128 * 4)               // 15360
#define SMEM_FLOATS (OFF_DSS + 128)                // 15488
#define SMEM_BYTES (SMEM_FLOATS * 4)               // 61952

// Fused edge kernel: FC0+sin -> smem H -> 3xTF32 MMA (lane-major W1 fragments)
// -> warp-local TP epilogue -> v4 RED scatter + edge update. 128 edges/block.
__global__ __launch_bounds__(128, 3) void edge_mma_kernel(
    const float* __restrict__ es, const int* __restrict__ src,
    const int* __restrict__ dst, const float* __restrict__ ea_in_p,
    float* __restrict__ ea_out_p, const float* __restrict__ fw0,
    const float* __restrict__ scew)
{
    extern __shared__ float sm[];
    float* Hs   = sm + OFF_HS;    // [128][68] row = edge, col = j (fp32 h)
    float* xs   = sm + OFF_XS;    // [128][36] x[src[e]]
    float* w0s  = sm + OFF_W0;    // FC0 weights
    float* sces = sm + OFF_SCE;   // sce weights
    float* eas  = sm + OFF_EAS;   // [128][4] edge attrs
    int*   dss  = (int*)(sm + OFF_DSS);  // [128] dst

    int tid = threadIdx.x;
    for (int i = tid; i < FCI * FCH; i += 128) w0s[i] = fw0[i];
    for (int i = tid; i < MUL * VE * VE; i += 128) sces[i] = scew[i];
    __syncthreads();

    const float* ea_in = ea_in_p ? ea_in_p : g_ea;
    float* ea_out = ea_out_p ? ea_out_p : g_ea;

    int ge = blockIdx.x * 128 + tid;   // NE = 128*6250, always in range

    // ---- h phase: FC0 + sin for this thread's edge ----
    {
        float scl[FCI];
        const float4* esp = (const float4*)(es + (size_t)ge * FCI);
#pragma unroll
        for (int i = 0; i < 4; i++) {
            float4 tv = esp[i];
            scl[4 * i + 0] = tv.x; scl[4 * i + 1] = tv.y;
            scl[4 * i + 2] = tv.z; scl[4 * i + 3] = tv.w;
        }
        float h[FCH];
#pragma unroll
        for (int j = 0; j < FCH; j++) h[j] = 0.0f;
#pragma unroll
        for (int i = 0; i < FCI; i++) {
            float si = scl[i];
            const float4* wr = (const float4*)&w0s[i * FCH];
#pragma unroll
            for (int j4 = 0; j4 < FCH / 4; j4++) {
                float4 wv = wr[j4];
                h[4 * j4 + 0] += si * wv.x;
                h[4 * j4 + 1] += si * wv.y;
                h[4 * j4 + 2] += si * wv.z;
                h[4 * j4 + 3] += si * wv.w;
            }
        }
        float4* hrow = (float4*)(Hs + tid * HS_STRIDE);
#pragma unroll
        for (int q = 0; q < 16; q++) {
            hrow[q] = make_float4(__sinf(h[4 * q + 0] * 0.25f), __sinf(h[4 * q + 1] * 0.25f),
                                  __sinf(h[4 * q + 2] * 0.25f), __sinf(h[4 * q + 3] * 0.25f));
        }
    }
    int sv = src[ge];
    dss[tid] = dst[ge];
    *(float4*)(eas + tid * 4) = *(const float4*)(ea_in + (size_t)ge * VE);
    {
        const float4* xr = (const float4*)(g_x + (size_t)sv * MUL);
        float4* xd = (float4*)(xs + tid * XS_STRIDE);
#pragma unroll
        for (int q = 0; q < 8; q++) xd[q] = xr[q];
    }
    __syncwarp();   // each warp only consumes rows written by its own threads

    // ---- MMA + epilogue: warp wp owns edges [32*wp, 32*wp+32) ----
    int lane = tid & 31, wp = tid >> 5, g = lane >> 2, t = lane & 3;

    float ear[2][2][4];
    int dlo[2], dhi[2];
#pragma unroll
    for (int mt = 0; mt < 2; mt++) {
        int rl = wp * 32 + mt * 16 + g, rh = rl + 8;
#pragma unroll
        for (int v = 0; v < 4; v++) {
            ear[mt][0][v] = eas[rl * 4 + v];
            ear[mt][1][v] = eas[rh * 4 + v];
        }
        dlo[mt] = dss[rl]; dhi[mt] = dss[rh];
    }

    float racc[2][2][4];
#pragma unroll
    for (int mt = 0; mt < 2; mt++)
#pragma unroll
        for (int i = 0; i < 2; i++)
#pragma unroll
            for (int v = 0; v < 4; v++) racc[mt][i][v] = 0.f;

    int vb = (2 * t) & 3;   // 0 or 2: v-base of this lane's acc pair

#pragma unroll 1
    for (int ng = 0; ng < 4; ng++) {
        float acc[2][4][4];
#pragma unroll
        for (int mt = 0; mt < 2; mt++)
#pragma unroll
            for (int nt = 0; nt < 4; nt++)
#pragma unroll
                for (int i = 0; i < 4; i++) acc[mt][nt][i] = 0.f;

#pragma unroll 1
        for (int k8 = 0; k8 < 8; k8++) {
            int k0 = k8 * 8;
            // B fragments: lane-major, coalesced LDG.64 (batched for MLP)
            int fb = ((ng * 8 + k8) * 4) * 32 + lane;
            uint2 bh[4], bl[4];
#pragma unroll
            for (int nt = 0; nt < 4; nt++) {
                bh[nt] = __ldg(&g_w1fhi[fb + nt * 32]);
                bl[nt] = __ldg(&g_w1flo[fb + nt * 32]);
            }
            // A fragments from smem H + in-loop split
            uint32_t ahi[2][4], alo[2][4];
#pragma unroll
            for (int mt = 0; mt < 2; mt++) {
                int rb = (wp * 32 + mt * 16 + g) * HS_STRIDE + k0 + t;
                tf32_split(Hs[rb],                     ahi[mt][0], alo[mt][0]);
                tf32_split(Hs[rb + 8 * HS_STRIDE],     ahi[mt][1], alo[mt][1]);
                tf32_split(Hs[rb + 4],                 ahi[mt][2], alo[mt][2]);
                tf32_split(Hs[rb + 8 * HS_STRIDE + 4], ahi[mt][3], alo[mt][3]);
            }
#pragma unroll
            for (int nt = 0; nt < 4; nt++) {
                uint32_t bhv[2] = {bh[nt].x, bh[nt].y};
                uint32_t blv[2] = {bl[nt].x, bl[nt].y};
#pragma unroll
                for (int mt = 0; mt < 2; mt++) {
                    mma_tf32(acc[mt][nt], ahi[mt], bhv);
                    mma_tf32(acc[mt][nt], ahi[mt], blv);
                    mma_tf32(acc[mt][nt], alo[mt], bhv);
                }
            }
        }

        // ---- epilogue for this n-group (u in [8*ng, 8*ng+8)) ----
#pragma unroll
        for (int mt = 0; mt < 2; mt++) {
            int rl = wp * 32 + mt * 16 + g, rh = rl + 8;
            float efl[4], efh[4];
#pragma unroll
            for (int nt = 0; nt < 4; nt++) {
                float* c = acc[mt][nt];
                float pl = ear[mt][0][vb] * c[0] + ear[mt][0][vb + 1] * c[1];
                float ph = ear[mt][1][vb] * c[2] + ear[mt][1][vb + 1] * c[3];
                pl += __shfl_xor_sync(0xffffffffu, pl, 1);
                ph += __shfl_xor_sync(0xffffffffu, ph, 1);
                int u = 8 * ng + 2 * nt + (t >> 1);
                float el = xs[rl * XS_STRIDE + u] * pl * 0.0625f;
                float eh = xs[rh * XS_STRIDE + u] * ph * 0.0625f;
                efl[nt] = el; efh[nt] = eh;
                // r accumulation (t-pairs duplicate; corrected by 0.5 at the end)
                const float4* sp = (const float4*)&sces[u * 16];
                float4 s0 = sp[0], s1 = sp[1], s2 = sp[2], s3 = sp[3];
                racc[mt][0][0] += el * (ear[mt][0][0] * s0.x + ear[mt][0][1] * s1.x + ear[mt][0][2] * s2.x + ear[mt][0][3] * s3.x);
                racc[mt][0][1] += el * (ear[mt][0][0] * s0.y + ear[mt][0][1] * s1.y + ear[mt][0][2] * s2.y + ear[mt][0][3] * s3.y);
                racc[mt][0][2] += el * (ear[mt][0][0] * s0.z + ear[mt][0][1] * s1.z + ear[mt][0][2] * s2.z + ear[mt][0][3] * s3.z);
                racc[mt][0][3] += el * (ear[mt][0][0] * s0.w + ear[mt][0][1] * s1.w + ear[mt][0][2] * s2.w + ear[mt][0][3] * s3.w);
                racc[mt][1][0] += eh * (ear[mt][1][0] * s0.x + ear[mt][1][1] * s1.x + ear[mt][1][2] * s2.x + ear[mt][1][3] * s3.x);
                racc[mt][1][1] += eh * (ear[mt][1][0] * s0.y + ear[mt][1][1] * s1.y + ear[mt][1][2] * s2.y + ear[mt][1][3] * s3.y);
                racc[mt][1][2] += eh * (ear[mt][1][0] * s0.z + ear[mt][1][1] * s1.z + ear[mt][1][2] * s2.z + ear[mt][1][3] * s3.z);
                racc[mt][1][3] += eh * (ear[mt][1][0] * s0.w + ear[mt][1][1] * s1.w + ear[mt][1][2] * s2.w + ear[mt][1][3] * s3.w);
            }
            // regroup u's for v4 RED: t0 has u{0,2,4,6}+8ng, t2 has u{1,3,5,7}+8ng
            float xl[4], xh[4];
#pragma unroll
            for (int nt = 0; nt < 4; nt++) {
                xl[nt] = __shfl_xor_sync(0xffffffffu, efl[nt], 2);
                xh[nt] = __shfl_xor_sync(0xffffffffu, efh[nt], 2);
            }
            if ((t & 1) == 0) {
                int ubase = 8 * ng + ((t == 0) ? 0 : 4);
                float a0, a1, a2, a3, b0, b1, b2, b3;
                if (t == 0) {
                    a0 = efl[0]; a1 = xl[0]; a2 = efl[1]; a3 = xl[1];
                    b0 = efh[0]; b1 = xh[0]; b2 = efh[1]; b3 = xh[1];
                } else {
                    a0 = xl[2]; a1 = efl[2]; a2 = xl[3]; a3 = efl[3];
                    b0 = xh[2]; b1 = efh[2]; b2 = xh[3]; b3 = efh[3];
                }
                const float sn = 0.25f;  // segment norm 1/sqrt(16)
                red_add_v4(&g_agg[(size_t)dlo[mt] * MUL + ubase], a0 * sn, a1 * sn, a2 * sn, a3 * sn);
                red_add_v4(&g_agg[(size_t)dhi[mt] * MUL + ubase], b0 * sn, b1 * sn, b2 * sn, b3 * sn);
            }
        }
    }

    // ---- finalize edge_out: reduce racc over the 4 lanes of the group ----
#pragma unroll
    for (int mt = 0; mt < 2; mt++)
#pragma unroll
        for (int i = 0; i < 2; i++)
#pragma unroll
            for (int v = 0; v < 4; v++) {
                float val = racc[mt][i][v];
                val += __shfl_xor_sync(0xffffffffu, val, 1);
                val += __shfl_xor_sync(0xffffffffu, val, 2);
                racc[mt][i][v] = val;
            }
    const float C2 = 0.5f * 0.022097086912079608f;  // 0.5 dup-fix * 1/(4*sqrt(128))
    if (t == 0) {
#pragma unroll
        for (int mt = 0; mt < 2; mt++) {
            int rl = wp * 32 + mt * 16 + g, rh = rl + 8;
            size_t el = (size_t)(blockIdx.x * 128 + rl);
            size_t eh = (size_t)(blockIdx.x * 128 + rh);
            float4 ol = make_float4(ear[mt][0][0] + racc[mt][0][0] * C2,
                                    ear[mt][0][1] + racc[mt][0][1] * C2,
                                    ear[mt][0][2] + racc[mt][0][2] * C2,
                                    ear[mt][0][3] + racc[mt][0][3] * C2);
            float4 oh = make_float4(ear[mt][1][0] + racc[mt][1][0] * C2,
                                    ear[mt][1][1] + racc[mt][1][1] * C2,
                                    ear[mt][1][2] + racc[mt][1][2] * C2,
                                    ear[mt][1][3] + racc[mt][1][3] * C2);
            *(float4*)(ea_out + el * VE) = ol;
            *(float4*)(ea_out + eh * VE) = oh;
        }
    }
}

// ---------------------------------------------------------------
extern "C" void kernel_launch(void* const* d_in, const int* in_sizes, int n_in,
                              void* d_out, int out_size)
{
    const float* node_features = (const float*)d_in[0];
    const float* node_attr     = (const float*)d_in[1];
    const int*   edge_src      = (const int*)d_in[2];
    const int*   edge_dst      = (const int*)d_in[3];
    const float* edge_attr     = (const float*)d_in[4];
    const float* edge_scalars  = (const float*)d_in[5];
    const float* sc_w    = (const float*)d_in[6];
    const float* lin1_w  = (const float*)d_in[7];
    const float* lin2_w  = (const float*)d_in[8];
    const float* alpha_w = (const float*)d_in[9];
    const float* sce_w   = (const float*)d_in[10];
    const float* fc_w0   = (const float*)d_in[11];
    const float* fc_w1   = (const float*)d_in[12];
    float* out = (float*)d_out;

    const int need_nf = NN * MUL;
    const int need_both = NN * MUL + NE * VE;
    float* nf_final = (out_size >= need_nf) ? out : nullptr;
    float* ea_final = (out_size >= need_both) ? (out + (size_t)NN * MUL) : nullptr;

    cudaFuncSetAttribute(edge_mma_kernel,
                         cudaFuncAttributeMaxDynamicSharedMemorySize, SMEM_BYTES);

    const int node_grid = (NN + 255) / 256;
    const int edge_grid = NE / 128;   // 6250
    const int zero_grid = (NN * MUL + 255) / 256;
    const int frag_grid = (4 * 8 * 4 * 32 + 255) / 256;   // 16

    for (int l = 0; l < 2; l++) {
        const float* nf_in = (l == 0) ? node_features : nullptr;  // null -> g_nf
        const float* ea_in = (l == 0) ? edge_attr : nullptr;      // null -> g_ea
        float* ea_out = (l == 1) ? ea_final : nullptr;            // null -> g_ea
        float* nf_out = (l == 1) ? nf_final : nullptr;            // null -> g_nf

        w1_frag_kernel<<<frag_grid, 256>>>(fc_w1 + (size_t)l * FCH * W_NUMEL);
        fctp_dual_kernel<<<2 * node_grid, 256>>>(nf_in, node_attr,
                                                 sc_w + (size_t)l * MUL * AA * MUL,
                                                 lin1_w + (size_t)l * MUL * AA * MUL,
                                                 node_grid);
        zero_agg_kernel<<<zero_grid, 256>>>();
        edge_mma_kernel<<<edge_grid, 128, SMEM_BYTES>>>(
            edge_scalars, edge_src, edge_dst, ea_in, ea_out,
            fc_w0 + (size_t)l * FCI * FCH,
            sce_w + (size_t)l * MUL * VE * VE);
        node_post_kernel<<<node_grid, 256>>>(node_attr,
                                             lin2_w + (size_t)l * MUL * AA * MUL,
                                             alpha_w + (size_t)l * MUL * AA,
                                             nf_out, (l == 0) ? 1 : 0);
    }
}

// round 13
// speedup vs baseline: 1.4494x; 1.4494x over previous
#include <cuda_runtime.h>
#include <math.h>
#include <stdint.h>

#define NN 50000
#define NE 800000
#define MUL 32
#define AA 8
#define VE 4
#define FCI 16
#define FCH 64
#define W_NUMEL 128

// ---------- scratch (device-code-only symbols; never passed from host) ----------
__device__ __align__(16) float g_x[NN * MUL];     // lin1 output
__device__ __align__(16) float g_sc[NN * MUL];    // self-connection output
__device__ __align__(16) float g_agg[NN * MUL];   // scatter-add accumulator
__device__ __align__(16) float g_nf[NN * MUL];    // node features between layers
__device__ __align__(16) float g_ea[NE * VE];     // edge attrs between layers
// lane-major pre-built tf32 B-fragments of W1^T: [(ng*8+k8)*4+nt][lane] -> (b0,b1)
__device__ __align__(16) uint2 g_w1fhi[4 * 8 * 4 * 32];
__device__ __align__(16) uint2 g_w1flo[4 * 8 * 4 * 32];

// ---------------------------------------------------------------
__global__ void zero_agg_kernel() {
    int i = blockIdx.x * blockDim.x + threadIdx.x;
    if (i < NN * MUL) g_agg[i] = 0.0f;
}

// ---------------- MMA helpers ----------------
__device__ __forceinline__ uint32_t f2tf32(float f) {
    uint32_t r;
    asm("cvt.rna.tf32.f32 %0, %1;" : "=r"(r) : "f"(f));
    return r;
}
__device__ __forceinline__ void tf32_split(float f, uint32_t& hi, uint32_t& lo) {
    hi = f2tf32(f);
    float res = f - __uint_as_float(hi);
    lo = f2tf32(res);
}
__device__ __forceinline__ void mma_tf32(float* c, const uint32_t* a, const uint32_t* b) {
    asm volatile(
        "mma.sync.aligned.m16n8k8.row.col.f32.tf32.tf32.f32 "
        "{%0,%1,%2,%3},{%4,%5,%6,%7},{%8,%9},{%0,%1,%2,%3};"
        : "+f"(c[0]), "+f"(c[1]), "+f"(c[2]), "+f"(c[3])
        : "r"(a[0]), "r"(a[1]), "r"(a[2]), "r"(a[3]), "r"(b[0]), "r"(b[1]));
}

// prep: build lane-major tf32 hi/lo B-fragments of W1^T.
// Fragment for lane (g,t) at (ng,k8,nt): n = 32*ng+8*nt+g, k = 8*k8+t,
// value = ( W1T[n][k], W1T[n][k+4] ), W1T[n][j] = fw1[j*128+n].
__global__ void w1_frag_kernel(const float* __restrict__ fw1) {
    int i = blockIdx.x * blockDim.x + threadIdx.x;   // 0 .. 4095
    if (i >= 4 * 8 * 4 * 32) return;
    int lane = i & 31, nt = (i >> 5) & 3, k8 = (i >> 7) & 7, ng = i >> 10;
    int g = lane >> 2, t = lane & 3;
    int n = 32 * ng + 8 * nt + g;
    int k = 8 * k8 + t;
    float f0 = fw1[k * W_NUMEL + n];
    float f1 = fw1[(k + 4) * W_NUMEL + n];
    uint32_t h0, l0, h1, l1;
    tf32_split(f0, h0, l0);
    tf32_split(f1, h1, l1);
    g_w1fhi[i] = make_uint2(h0, h1);
    g_w1flo[i] = make_uint2(l0, l1);
}

// Dual fctp: blocks [0, ng) compute sc_w -> g_sc ; blocks [ng, 2ng) compute lin1_w -> g_x
__global__ __launch_bounds__(256) void fctp_dual_kernel(
    const float* __restrict__ a, const float* __restrict__ b,
    const float* __restrict__ w_sc, const float* __restrict__ w_lin1, int ng)
{
    __shared__ float ws[MUL * AA * MUL];  // 32KB
    int half = (blockIdx.x >= ng) ? 1 : 0;
    const float* w = half ? w_lin1 : w_sc;
    for (int i = threadIdx.x; i < MUL * AA * MUL; i += 256) ws[i] = w[i];
    __syncthreads();

    int blk = half ? (blockIdx.x - ng) : blockIdx.x;
    int n = blk * 256 + threadIdx.x;
    if (n >= NN) return;
    const float* ap = a ? a : g_nf;
    float* out = half ? g_x : g_sc;

    float attr[AA];
#pragma unroll
    for (int v = 0; v < AA; v++) attr[v] = b[n * AA + v];

    float4 acc4[8];
#pragma unroll
    for (int k4 = 0; k4 < 8; k4++) acc4[k4] = make_float4(0.f, 0.f, 0.f, 0.f);

    const float4* arow = (const float4*)(ap + (size_t)n * MUL);
    for (int u4 = 0; u4 < 8; u4++) {
        float4 av = arow[u4];
        float au[4] = {av.x, av.y, av.z, av.w};
#pragma unroll
        for (int uu = 0; uu < 4; uu++) {
            int u = u4 * 4 + uu;
#pragma unroll
            for (int v = 0; v < AA; v++) {
                float p = au[uu] * attr[v];
                const float4* wp = (const float4*)&ws[(u * AA + v) * MUL];
#pragma unroll
                for (int k4 = 0; k4 < 8; k4++) {
                    float4 wv = wp[k4];
                    acc4[k4].x += p * wv.x;
                    acc4[k4].y += p * wv.y;
                    acc4[k4].z += p * wv.z;
                    acc4[k4].w += p * wv.w;
                }
            }
        }
    }
    const float s = 1.0f / 16.0f;
    float4* op = (float4*)(out + (size_t)n * MUL);
#pragma unroll
    for (int k4 = 0; k4 < 8; k4++) {
        float4 o = acc4[k4];
        o.x *= s; o.y *= s; o.z *= s; o.w *= s;
        op[k4] = o;
    }
}

// lin2 + alpha + combine (+ optional sin). out == nullptr -> write g_nf
__global__ __launch_bounds__(256) void node_post_kernel(
    const float* __restrict__ b, const float* __restrict__ lin2w,
    const float* __restrict__ alw, float* __restrict__ out, int apply_sin)
{
    __shared__ float ws[MUL * AA * MUL];  // 32KB
    __shared__ float as[MUL * AA];        // 1KB
    for (int i = threadIdx.x; i < MUL * AA * MUL; i += 256) ws[i] = lin2w[i];
    for (int i = threadIdx.x; i < MUL * AA; i += 256) as[i] = alw[i];
    __syncthreads();

    int n = blockIdx.x * 256 + threadIdx.x;
    if (n >= NN) return;
    float* op = out ? out : g_nf;

    float attr[AA];
#pragma unroll
    for (int v = 0; v < AA; v++) attr[v] = b[n * AA + v];

    float4 acc4[8];
#pragma unroll
    for (int k4 = 0; k4 < 8; k4++) acc4[k4] = make_float4(0.f, 0.f, 0.f, 0.f);
    float aacc = 0.0f;

    const float4* arow = (const float4*)(g_agg + (size_t)n * MUL);
    for (int u4 = 0; u4 < 8; u4++) {
        float4 av = arow[u4];
        float au[4] = {av.x, av.y, av.z, av.w};
#pragma unroll
        for (int uu = 0; uu < 4; uu++) {
            int u = u4 * 4 + uu;
#pragma unroll
            for (int v = 0; v < AA; v++) {
                float p = au[uu] * attr[v];
                aacc += p * as[u * AA + v];
                const float4* wp = (const float4*)&ws[(u * AA + v) * MUL];
#pragma unroll
                for (int k4 = 0; k4 < 8; k4++) {
                    float4 wv = wp[k4];
                    acc4[k4].x += p * wv.x;
                    acc4[k4].y += p * wv.y;
                    acc4[k4].z += p * wv.z;
                    acc4[k4].w += p * wv.w;
                }
            }
        }
    }
    const float s = 1.0f / 16.0f;
    float alpha = aacc * s;
    const float4* scp = (const float4*)(g_sc + (size_t)n * MUL);
    float4* outp = (float4*)(op + (size_t)n * MUL);
#pragma unroll
    for (int k4 = 0; k4 < 8; k4++) {
        float4 sc = scp[k4];
        float4 cv = acc4[k4];
        float4 o;
        o.x = sc.x + alpha * (cv.x * s);
        o.y = sc.y + alpha * (cv.y * s);
        o.z = sc.z + alpha * (cv.z * s);
        o.w = sc.w + alpha * (cv.w * s);
        if (apply_sin) { o.x = sinf(o.x); o.y = sinf(o.y); o.z = sinf(o.z); o.w = sinf(o.w); }
        outp[k4] = o;
    }
}

// 16B-aligned 4-wide global float add (native vector atomic on sm_90+).
__device__ __forceinline__ void red_add_v4(float* ptr, float a, float b, float c, float d)
{
#if defined(__CUDA_ARCH__) && (__CUDA_ARCH__ >= 900) && (CUDART_VERSION >= 12080)
    atomicAdd((float4*)ptr, make_float4(a, b, c, d));
#else
    atomicAdd(ptr + 0, a);
    atomicAdd(ptr + 1, b);
    atomicAdd(ptr + 2, c);
    atomicAdd(ptr + 3, d);
#endif
}

// smem layout (floats/words) for edge_mma_kernel
#define HS_STRIDE 68
#define XS_STRIDE 36
#define OFF_HS   0
#define OFF_XS   (128 * HS_STRIDE)                 // 8704
#define OFF_W0   (OFF_XS + 128 * XS_STRIDE)        // 13312
#define OFF_SCE  (OFF_W0 + FCI * FCH)              // 14336
#define OFF_EAS  (OFF_SCE + MUL * VE * VE)         // 14848
#define OFF_DSS  (OFF_EAS + 128 * 4)               // 15360
#define SMEM_FLOATS (OFF_DSS + 128)                // 15488
#define SMEM_BYTES (SMEM_FLOATS * 4)               // 61952

// Fused edge kernel, 256 threads / 128 edges per block, 8 warps x 16 edges.
// h-phase: 2 threads/edge (half-j each), h stored PRE-CONVERTED to tf32 bits.
// MMA: A single tf32 x B (hi+lo planes) = 2 MMAs per step.
__global__ __launch_bounds__(256, 2) void edge_mma_kernel(
    const float* __restrict__ es, const int* __restrict__ src,
    const int* __restrict__ dst, const float* __restrict__ ea_in_p,
    float* __restrict__ ea_out_p, const float* __restrict__ fw0,
    const float* __restrict__ scew)
{
    extern __shared__ float sm[];
    uint32_t* Hs = (uint32_t*)(sm + OFF_HS);   // [128][68] tf32 bits of h
    float* xs   = sm + OFF_XS;    // [128][36] x[src[e]]
    float* w0s  = sm + OFF_W0;    // FC0 weights
    float* sces = sm + OFF_SCE;   // sce weights
    float* eas  = sm + OFF_EAS;   // [128][4] edge attrs
    int*   dss  = (int*)(sm + OFF_DSS);  // [128] dst

    int tid = threadIdx.x;
    for (int i = tid; i < FCI * FCH; i += 256) w0s[i] = fw0[i];
    for (int i = tid; i < MUL * VE * VE; i += 256) sces[i] = scew[i];
    __syncthreads();

    const float* ea_in = ea_in_p ? ea_in_p : g_ea;
    float* ea_out = ea_out_p ? ea_out_p : g_ea;

    // ---- h phase: 2 threads per edge, each computes 32 of the 64 h values ----
    {
        int e = tid & 127, jh = tid >> 7;
        int ge = blockIdx.x * 128 + e;
        float scl[FCI];
        const float4* esp = (const float4*)(es + (size_t)ge * FCI);
#pragma unroll
        for (int i = 0; i < 4; i++) {
            float4 tv = esp[i];
            scl[4 * i + 0] = tv.x; scl[4 * i + 1] = tv.y;
            scl[4 * i + 2] = tv.z; scl[4 * i + 3] = tv.w;
        }
        float h[32];
#pragma unroll
        for (int j = 0; j < 32; j++) h[j] = 0.0f;
#pragma unroll
        for (int i = 0; i < FCI; i++) {
            float si = scl[i];
            const float4* wr = (const float4*)&w0s[i * FCH + 32 * jh];
#pragma unroll
            for (int j4 = 0; j4 < 8; j4++) {
                float4 wv = wr[j4];
                h[4 * j4 + 0] += si * wv.x;
                h[4 * j4 + 1] += si * wv.y;
                h[4 * j4 + 2] += si * wv.z;
                h[4 * j4 + 3] += si * wv.w;
            }
        }
        uint4* hrow = (uint4*)(Hs + e * HS_STRIDE + 32 * jh);
#pragma unroll
        for (int q = 0; q < 8; q++) {
            uint4 pk;
            pk.x = f2tf32(__sinf(h[4 * q + 0] * 0.25f));
            pk.y = f2tf32(__sinf(h[4 * q + 1] * 0.25f));
            pk.z = f2tf32(__sinf(h[4 * q + 2] * 0.25f));
            pk.w = f2tf32(__sinf(h[4 * q + 3] * 0.25f));
            hrow[q] = pk;
        }
        if (jh == 0) {
            dss[e] = dst[ge];
            *(float4*)(eas + e * 4) = *(const float4*)(ea_in + (size_t)ge * VE);
            int sv = src[ge];
            const float4* xr = (const float4*)(g_x + (size_t)sv * MUL);
            float4* xd = (float4*)(xs + e * XS_STRIDE);
#pragma unroll
            for (int q = 0; q < 8; q++) xd[q] = xr[q];
        }
    }
    __syncthreads();

    // ---- MMA + epilogue: warp wp owns edges [16*wp, 16*wp+16) ----
    int lane = tid & 31, wp = tid >> 5, g = lane >> 2, t = lane & 3;
    int r0 = wp * 16 + g;     // low row (block-local edge index)
    int r1 = r0 + 8;          // high row

    float ear[2][4];
#pragma unroll
    for (int v = 0; v < 4; v++) {
        ear[0][v] = eas[r0 * 4 + v];
        ear[1][v] = eas[r1 * 4 + v];
    }
    int d0 = dss[r0], d1 = dss[r1];

    float racc[2][4];
#pragma unroll
    for (int i = 0; i < 2; i++)
#pragma unroll
        for (int v = 0; v < 4; v++) racc[i][v] = 0.f;

    int vb = (2 * t) & 3;   // 0 or 2: v-base of this lane's acc pair

#pragma unroll 1
    for (int ng = 0; ng < 4; ng++) {
        float acc[4][4];
#pragma unroll
        for (int nt = 0; nt < 4; nt++)
#pragma unroll
            for (int i = 0; i < 4; i++) acc[nt][i] = 0.f;

#pragma unroll 1
        for (int k8 = 0; k8 < 8; k8++) {
            // B fragments: lane-major, coalesced LDG.64 (batched for MLP)
            int fb = ((ng * 8 + k8) * 4) * 32 + lane;
            uint2 bh[4], bl[4];
#pragma unroll
            for (int nt = 0; nt < 4; nt++) {
                bh[nt] = __ldg(&g_w1fhi[fb + nt * 32]);
                bl[nt] = __ldg(&g_w1flo[fb + nt * 32]);
            }
            // A fragments: pre-converted tf32 bits straight from smem
            int rb = r0 * HS_STRIDE + k8 * 8 + t;
            uint32_t a[4];
            a[0] = Hs[rb];
            a[1] = Hs[rb + 8 * HS_STRIDE];
            a[2] = Hs[rb + 4];
            a[3] = Hs[rb + 8 * HS_STRIDE + 4];
#pragma unroll
            for (int nt = 0; nt < 4; nt++) {
                uint32_t bhv[2] = {bh[nt].x, bh[nt].y};
                uint32_t blv[2] = {bl[nt].x, bl[nt].y};
                mma_tf32(acc[nt], a, bhv);
                mma_tf32(acc[nt], a, blv);
            }
        }

        // ---- epilogue for this n-group (u in [8*ng, 8*ng+8)) ----
        float efl[4], efh[4];
#pragma unroll
        for (int nt = 0; nt < 4; nt++) {
            float* c = acc[nt];
            float pl = ear[0][vb] * c[0] + ear[0][vb + 1] * c[1];
            float ph = ear[1][vb] * c[2] + ear[1][vb + 1] * c[3];
            pl += __shfl_xor_sync(0xffffffffu, pl, 1);
            ph += __shfl_xor_sync(0xffffffffu, ph, 1);
            int u = 8 * ng + 2 * nt + (t >> 1);
            float el = xs[r0 * XS_STRIDE + u] * pl * 0.0625f;
            float eh = xs[r1 * XS_STRIDE + u] * ph * 0.0625f;
            efl[nt] = el; efh[nt] = eh;
            // r accumulation (t-pairs duplicate; corrected by 0.5 at the end)
            const float4* sp = (const float4*)&sces[u * 16];
            float4 s0 = sp[0], s1 = sp[1], s2 = sp[2], s3 = sp[3];
            racc[0][0] += el * (ear[0][0] * s0.x + ear[0][1] * s1.x + ear[0][2] * s2.x + ear[0][3] * s3.x);
            racc[0][1] += el * (ear[0][0] * s0.y + ear[0][1] * s1.y + ear[0][2] * s2.y + ear[0][3] * s3.y);
            racc[0][2] += el * (ear[0][0] * s0.z + ear[0][1] * s1.z + ear[0][2] * s2.z + ear[0][3] * s3.z);
            racc[0][3] += el * (ear[0][0] * s0.w + ear[0][1] * s1.w + ear[0][2] * s2.w + ear[0][3] * s3.w);
            racc[1][0] += eh * (ear[1][0] * s0.x + ear[1][1] * s1.x + ear[1][2] * s2.x + ear[1][3] * s3.x);
            racc[1][1] += eh * (ear[1][0] * s0.y + ear[1][1] * s1.y + ear[1][2] * s2.y + ear[1][3] * s3.y);
            racc[1][2] += eh * (ear[1][0] * s0.z + ear[1][1] * s1.z + ear[1][2] * s2.z + ear[1][3] * s3.z);
            racc[1][3] += eh * (ear[1][0] * s0.w + ear[1][1] * s1.w + ear[1][2] * s2.w + ear[1][3] * s3.w);
        }
        // regroup u's for v4 RED: t0 -> u{0..3}+8ng, t2 -> u{4..7}+8ng
        float xl[4], xh[4];
#pragma unroll
        for (int nt = 0; nt < 4; nt++) {
            xl[nt] = __shfl_xor_sync(0xffffffffu, efl[nt], 2);
            xh[nt] = __shfl_xor_sync(0xffffffffu, efh[nt], 2);
        }
        if ((t & 1) == 0) {
            int ubase = 8 * ng + ((t == 0) ? 0 : 4);
            float a0, a1, a2, a3, b0, b1, b2, b3;
            if (t == 0) {
                a0 = efl[0]; a1 = xl[0]; a2 = efl[1]; a3 = xl[1];
                b0 = efh[0]; b1 = xh[0]; b2 = efh[1]; b3 = xh[1];
            } else {
                a0 = xl[2]; a1 = efl[2]; a2 = xl[3]; a3 = efl[3];
                b0 = xh[2]; b1 = efh[2]; b2 = xh[3]; b3 = efh[3];
            }
            const float sn = 0.25f;  // segment norm 1/sqrt(16)
            red_add_v4(&g_agg[(size_t)d0 * MUL + ubase], a0 * sn, a1 * sn, a2 * sn, a3 * sn);
            red_add_v4(&g_agg[(size_t)d1 * MUL + ubase], b0 * sn, b1 * sn, b2 * sn, b3 * sn);
        }
    }

    // ---- finalize edge_out: reduce racc over the 4 lanes of the group ----
#pragma unroll
    for (int i = 0; i < 2; i++)
#pragma unroll
        for (int v = 0; v < 4; v++) {
            float val = racc[i][v];
            val += __shfl_xor_sync(0xffffffffu, val, 1);
            val += __shfl_xor_sync(0xffffffffu, val, 2);
            racc[i][v] = val;
        }
    const float C2 = 0.5f * 0.022097086912079608f;  // 0.5 dup-fix * 1/(4*sqrt(128))
    if (t == 0) {
        size_t el = (size_t)(blockIdx.x * 128 + r0);
        size_t eh = (size_t)(blockIdx.x * 128 + r1);
        float4 ol = make_float4(ear[0][0] + racc[0][0] * C2,
                                ear[0][1] + racc[0][1] * C2,
                                ear[0][2] + racc[0][2] * C2,
                                ear[0][3] + racc[0][3] * C2);
        float4 oh = make_float4(ear[1][0] + racc[1][0] * C2,
                                ear[1][1] + racc[1][1] * C2,
                                ear[1][2] + racc[1][2] * C2,
                                ear[1][3] + racc[1][3] * C2);
        *(float4*)(ea_out + el * VE) = ol;
        *(float4*)(ea_out + eh * VE) = oh;
    }
}

// ---------------------------------------------------------------
extern "C" void kernel_launch(void* const* d_in, const int* in_sizes, int n_in,
                              void* d_out, int out_size)
{
    const float* node_features = (const float*)d_in[0];
    const float* node_attr     = (const float*)d_in[1];
    const int*   edge_src      = (const int*)d_in[2];
    const int*   edge_dst      = (const int*)d_in[3];
    const float* edge_attr     = (const float*)d_in[4];
    const float* edge_scalars  = (const float*)d_in[5];
    const float* sc_w    = (const float*)d_in[6];
    const float* lin1_w  = (const float*)d_in[7];
    const float* lin2_w  = (const float*)d_in[8];
    const float* alpha_w = (const float*)d_in[9];
    const float* sce_w   = (const float*)d_in[10];
    const float* fc_w0   = (const float*)d_in[11];
    const float* fc_w1   = (const float*)d_in[12];
    float* out = (float*)d_out;

    const int need_nf = NN * MUL;
    const int need_both = NN * MUL + NE * VE;
    float* nf_final = (out_size >= need_nf) ? out : nullptr;
    float* ea_final = (out_size >= need_both) ? (out + (size_t)NN * MUL) : nullptr;

    cudaFuncSetAttribute(edge_mma_kernel,
                         cudaFuncAttributeMaxDynamicSharedMemorySize, SMEM_BYTES);

    const int node_grid = (NN + 255) / 256;
    const int edge_grid = NE / 128;   // 6250 blocks x 256 threads
    const int zero_grid = (NN * MUL + 255) / 256;
    const int frag_grid = (4 * 8 * 4 * 32 + 255) / 256;   // 16

    for (int l = 0; l < 2; l++) {
        const float* nf_in = (l == 0) ? node_features : nullptr;  // null -> g_nf
        const float* ea_in = (l == 0) ? edge_attr : nullptr;      // null -> g_ea
        float* ea_out = (l == 1) ? ea_final : nullptr;            // null -> g_ea
        float* nf_out = (l == 1) ? nf_final : nullptr;            // null -> g_nf

        w1_frag_kernel<<<frag_grid, 256>>>(fc_w1 + (size_t)l * FCH * W_NUMEL);
        fctp_dual_kernel<<<2 * node_grid, 256>>>(nf_in, node_attr,
                                                 sc_w + (size_t)l * MUL * AA * MUL,
                                                 lin1_w + (size_t)l * MUL * AA * MUL,
                                                 node_grid);
        zero_agg_kernel<<<zero_grid, 256>>>();
        edge_mma_kernel<<<edge_grid, 256, SMEM_BYTES>>>(
            edge_scalars, edge_src, edge_dst, ea_in, ea_out,
            fc_w0 + (size_t)l * FCI * FCH,
            sce_w + (size_t)l * MUL * VE * VE);
        node_post_kernel<<<node_grid, 256>>>(node_attr,
                                             lin2_w + (size_t)l * MUL * AA * MUL,
                                             alpha_w + (size_t)l * MUL * AA,
                                             nf_out, (l == 0) ? 1 : 0);
    }
}

// round 14
// speedup vs baseline: 1.7883x; 1.2339x over previous
#include <cuda_runtime.h>
#include <math.h>
#include <stdint.h>

#define NN 50000
#define NE 800000
#define MUL 32
#define AA 8
#define VE 4
#define FCI 16
#define FCH 64
#define W_NUMEL 128

// ---------- scratch (device-code-only symbols; never passed from host) ----------
__device__ __align__(16) float g_x[NN * MUL];     // lin1 output
__device__ __align__(16) float g_sc[NN * MUL];    // self-connection output
__device__ __align__(16) float g_agg[NN * MUL];   // scatter-add accumulator
__device__ __align__(16) float g_nf[NN * MUL];    // node features between layers
__device__ __align__(16) float g_ea[NE * VE];     // edge attrs between layers
// lane-major pre-built tf32 B-fragments of W1^T: [(ng*8+k8)*4+nt][lane] -> (b0,b1)
__device__ __align__(16) uint2 g_w1f[4 * 8 * 4 * 32];

// ---------------------------------------------------------------
__global__ void zero_agg_kernel() {
    int i = blockIdx.x * blockDim.x + threadIdx.x;
    if (i < NN * MUL) g_agg[i] = 0.0f;
}

// ---------------- MMA helpers ----------------
__device__ __forceinline__ uint32_t f2tf32(float f) {
    uint32_t r;
    asm("cvt.rna.tf32.f32 %0, %1;" : "=r"(r) : "f"(f));
    return r;
}
__device__ __forceinline__ void mma_tf32(float* c, const uint32_t* a, const uint32_t* b) {
    asm volatile(
        "mma.sync.aligned.m16n8k8.row.col.f32.tf32.tf32.f32 "
        "{%0,%1,%2,%3},{%4,%5,%6,%7},{%8,%9},{%0,%1,%2,%3};"
        : "+f"(c[0]), "+f"(c[1]), "+f"(c[2]), "+f"(c[3])
        : "r"(a[0]), "r"(a[1]), "r"(a[2]), "r"(a[3]), "r"(b[0]), "r"(b[1]));
}

// prep: build lane-major tf32 B-fragments of W1^T (single hi plane).
// Fragment for lane (g,t) at (ng,k8,nt): n = 32*ng+8*nt+g, k = 8*k8+t,
// value = ( W1T[n][k], W1T[n][k+4] ), W1T[n][j] = fw1[j*128+n].
__global__ void w1_frag_kernel(const float* __restrict__ fw1) {
    int i = blockIdx.x * blockDim.x + threadIdx.x;   // 0 .. 4095
    if (i >= 4 * 8 * 4 * 32) return;
    int lane = i & 31, nt = (i >> 5) & 3, k8 = (i >> 7) & 7, ng = i >> 10;
    int g = lane >> 2, t = lane & 3;
    int n = 32 * ng + 8 * nt + g;
    int k = 8 * k8 + t;
    g_w1f[i] = make_uint2(f2tf32(fw1[k * W_NUMEL + n]),
                          f2tf32(fw1[(k + 4) * W_NUMEL + n]));
}

// Dual fctp: blocks [0, ng) compute sc_w -> g_sc ; blocks [ng, 2ng) compute lin1_w -> g_x
__global__ __launch_bounds__(256) void fctp_dual_kernel(
    const float* __restrict__ a, const float* __restrict__ b,
    const float* __restrict__ w_sc, const float* __restrict__ w_lin1, int ng)
{
    __shared__ float ws[MUL * AA * MUL];  // 32KB
    int half = (blockIdx.x >= ng) ? 1 : 0;
    const float* w = half ? w_lin1 : w_sc;
    for (int i = threadIdx.x; i < MUL * AA * MUL; i += 256) ws[i] = w[i];
    __syncthreads();

    int blk = half ? (blockIdx.x - ng) : blockIdx.x;
    int n = blk * 256 + threadIdx.x;
    if (n >= NN) return;
    const float* ap = a ? a : g_nf;
    float* out = half ? g_x : g_sc;

    float attr[AA];
#pragma unroll
    for (int v = 0; v < AA; v++) attr[v] = b[n * AA + v];

    float4 acc4[8];
#pragma unroll
    for (int k4 = 0; k4 < 8; k4++) acc4[k4] = make_float4(0.f, 0.f, 0.f, 0.f);

    const float4* arow = (const float4*)(ap + (size_t)n * MUL);
    for (int u4 = 0; u4 < 8; u4++) {
        float4 av = arow[u4];
        float au[4] = {av.x, av.y, av.z, av.w};
#pragma unroll
        for (int uu = 0; uu < 4; uu++) {
            int u = u4 * 4 + uu;
#pragma unroll
            for (int v = 0; v < AA; v++) {
                float p = au[uu] * attr[v];
                const float4* wp = (const float4*)&ws[(u * AA + v) * MUL];
#pragma unroll
                for (int k4 = 0; k4 < 8; k4++) {
                    float4 wv = wp[k4];
                    acc4[k4].x += p * wv.x;
                    acc4[k4].y += p * wv.y;
                    acc4[k4].z += p * wv.z;
                    acc4[k4].w += p * wv.w;
                }
            }
        }
    }
    const float s = 1.0f / 16.0f;
    float4* op = (float4*)(out + (size_t)n * MUL);
#pragma unroll
    for (int k4 = 0; k4 < 8; k4++) {
        float4 o = acc4[k4];
        o.x *= s; o.y *= s; o.z *= s; o.w *= s;
        op[k4] = o;
    }
}

// lin2 + alpha + combine (+ optional sin). out == nullptr -> write g_nf
__global__ __launch_bounds__(256) void node_post_kernel(
    const float* __restrict__ b, const float* __restrict__ lin2w,
    const float* __restrict__ alw, float* __restrict__ out, int apply_sin)
{
    __shared__ float ws[MUL * AA * MUL];  // 32KB
    __shared__ float as[MUL * AA];        // 1KB
    for (int i = threadIdx.x; i < MUL * AA * MUL; i += 256) ws[i] = lin2w[i];
    for (int i = threadIdx.x; i < MUL * AA; i += 256) as[i] = alw[i];
    __syncthreads();

    int n = blockIdx.x * 256 + threadIdx.x;
    if (n >= NN) return;
    float* op = out ? out : g_nf;

    float attr[AA];
#pragma unroll
    for (int v = 0; v < AA; v++) attr[v] = b[n * AA + v];

    float4 acc4[8];
#pragma unroll
    for (int k4 = 0; k4 < 8; k4++) acc4[k4] = make_float4(0.f, 0.f, 0.f, 0.f);
    float aacc = 0.0f;

    const float4* arow = (const float4*)(g_agg + (size_t)n * MUL);
    for (int u4 = 0; u4 < 8; u4++) {
        float4 av = arow[u4];
        float au[4] = {av.x, av.y, av.z, av.w};
#pragma unroll
        for (int uu = 0; uu < 4; uu++) {
            int u = u4 * 4 + uu;
#pragma unroll
            for (int v = 0; v < AA; v++) {
                float p = au[uu] * attr[v];
                aacc += p * as[u * AA + v];
                const float4* wp = (const float4*)&ws[(u * AA + v) * MUL];
#pragma unroll
                for (int k4 = 0; k4 < 8; k4++) {
                    float4 wv = wp[k4];
                    acc4[k4].x += p * wv.x;
                    acc4[k4].y += p * wv.y;
                    acc4[k4].z += p * wv.z;
                    acc4[k4].w += p * wv.w;
                }
            }
        }
    }
    const float s = 1.0f / 16.0f;
    float alpha = aacc * s;
    const float4* scp = (const float4*)(g_sc + (size_t)n * MUL);
    float4* outp = (float4*)(op + (size_t)n * MUL);
#pragma unroll
    for (int k4 = 0; k4 < 8; k4++) {
        float4 sc = scp[k4];
        float4 cv = acc4[k4];
        float4 o;
        o.x = sc.x + alpha * (cv.x * s);
        o.y = sc.y + alpha * (cv.y * s);
        o.z = sc.z + alpha * (cv.z * s);
        o.w = sc.w + alpha * (cv.w * s);
        if (apply_sin) { o.x = sinf(o.x); o.y = sinf(o.y); o.z = sinf(o.z); o.w = sinf(o.w); }
        outp[k4] = o;
    }
}

// 16B-aligned 4-wide global float add (native vector atomic on sm_90+).
__device__ __forceinline__ void red_add_v4(float* ptr, float a, float b, float c, float d)
{
#if defined(__CUDA_ARCH__) && (__CUDA_ARCH__ >= 900) && (CUDART_VERSION >= 12080)
    atomicAdd((float4*)ptr, make_float4(a, b, c, d));
#else
    atomicAdd(ptr + 0, a);
    atomicAdd(ptr + 1, b);
    atomicAdd(ptr + 2, c);
    atomicAdd(ptr + 3, d);
#endif
}

// smem layout (floats/words) for edge_mma_kernel
#define HS_STRIDE 68
#define XS_STRIDE 36
#define OFF_HS   0
#define OFF_XS   (128 * HS_STRIDE)                 // 8704
#define OFF_W0   (OFF_XS + 128 * XS_STRIDE)        // 13312
#define OFF_SCE  (OFF_W0 + FCI * FCH)              // 14336
#define OFF_EAS  (OFF_SCE + MUL * VE * VE)         // 14848
#define OFF_DSS  (OFF_EAS + 128 * 4)               // 15360
#define SMEM_FLOATS (OFF_DSS + 128)                // 15488
#define SMEM_BYTES (SMEM_FLOATS * 4)               // 61952

// Fused edge kernel, 256 threads / 128 edges per block, 8 warps x 16 edges.
// h-phase: 2 threads/edge, h stored PRE-CONVERTED to tf32 bits.
// MMA: single tf32 x tf32 per step (1 MMA). 3 blocks/SM target.
__global__ __launch_bounds__(256, 3) void edge_mma_kernel(
    const float* __restrict__ es, const int* __restrict__ src,
    const int* __restrict__ dst, const float* __restrict__ ea_in_p,
    float* __restrict__ ea_out_p, const float* __restrict__ fw0,
    const float* __restrict__ scew)
{
    extern __shared__ float sm[];
    uint32_t* Hs = (uint32_t*)(sm + OFF_HS);   // [128][68] tf32 bits of h
    float* xs   = sm + OFF_XS;    // [128][36] x[src[e]]
    float* w0s  = sm + OFF_W0;    // FC0 weights
    float* sces = sm + OFF_SCE;   // sce weights
    float* eas  = sm + OFF_EAS;   // [128][4] edge attrs
    int*   dss  = (int*)(sm + OFF_DSS);  // [128] dst

    int tid = threadIdx.x;
    for (int i = tid; i < FCI * FCH; i += 256) w0s[i] = fw0[i];
    for (int i = tid; i < MUL * VE * VE; i += 256) sces[i] = scew[i];
    __syncthreads();

    const float* ea_in = ea_in_p ? ea_in_p : g_ea;
    float* ea_out = ea_out_p ? ea_out_p : g_ea;

    // ---- h phase: 2 threads per edge, each computes 32 of the 64 h values ----
    {
        int e = tid & 127, jh = tid >> 7;
        int ge = blockIdx.x * 128 + e;
        float scl[FCI];
        const float4* esp = (const float4*)(es + (size_t)ge * FCI);
#pragma unroll
        for (int i = 0; i < 4; i++) {
            float4 tv = esp[i];
            scl[4 * i + 0] = tv.x; scl[4 * i + 1] = tv.y;
            scl[4 * i + 2] = tv.z; scl[4 * i + 3] = tv.w;
        }
        float h[32];
#pragma unroll
        for (int j = 0; j < 32; j++) h[j] = 0.0f;
#pragma unroll
        for (int i = 0; i < FCI; i++) {
            float si = scl[i];
            const float4* wr = (const float4*)&w0s[i * FCH + 32 * jh];
#pragma unroll
            for (int j4 = 0; j4 < 8; j4++) {
                float4 wv = wr[j4];
                h[4 * j4 + 0] += si * wv.x;
                h[4 * j4 + 1] += si * wv.y;
                h[4 * j4 + 2] += si * wv.z;
                h[4 * j4 + 3] += si * wv.w;
            }
        }
        uint4* hrow = (uint4*)(Hs + e * HS_STRIDE + 32 * jh);
#pragma unroll
        for (int q = 0; q < 8; q++) {
            uint4 pk;
            pk.x = f2tf32(__sinf(h[4 * q + 0] * 0.25f));
            pk.y = f2tf32(__sinf(h[4 * q + 1] * 0.25f));
            pk.z = f2tf32(__sinf(h[4 * q + 2] * 0.25f));
            pk.w = f2tf32(__sinf(h[4 * q + 3] * 0.25f));
            hrow[q] = pk;
        }
        if (jh == 0) {
            dss[e] = dst[ge];
            *(float4*)(eas + e * 4) = *(const float4*)(ea_in + (size_t)ge * VE);
            int sv = src[ge];
            const float4* xr = (const float4*)(g_x + (size_t)sv * MUL);
            float4* xd = (float4*)(xs + e * XS_STRIDE);
#pragma unroll
            for (int q = 0; q < 8; q++) xd[q] = xr[q];
        }
    }
    __syncthreads();

    // ---- MMA + epilogue: warp wp owns edges [16*wp, 16*wp+16) ----
    int lane = tid & 31, wp = tid >> 5, g = lane >> 2, t = lane & 3;
    int r0 = wp * 16 + g;     // low row (block-local edge index)
    int r1 = r0 + 8;          // high row

    float ear[2][4];
#pragma unroll
    for (int v = 0; v < 4; v++) {
        ear[0][v] = eas[r0 * 4 + v];
        ear[1][v] = eas[r1 * 4 + v];
    }
    int d0 = dss[r0], d1 = dss[r1];

    float racc[2][4];
#pragma unroll
    for (int i = 0; i < 2; i++)
#pragma unroll
        for (int v = 0; v < 4; v++) racc[i][v] = 0.f;

    int vb = (2 * t) & 3;   // 0 or 2: v-base of this lane's acc pair

#pragma unroll 1
    for (int ng = 0; ng < 4; ng++) {
        float acc[4][4];
#pragma unroll
        for (int nt = 0; nt < 4; nt++)
#pragma unroll
            for (int i = 0; i < 4; i++) acc[nt][i] = 0.f;

#pragma unroll 1
        for (int k8 = 0; k8 < 8; k8++) {
            // B fragments: lane-major, coalesced LDG.64 (batched for MLP)
            int fb = ((ng * 8 + k8) * 4) * 32 + lane;
            uint2 bh[4];
#pragma unroll
            for (int nt = 0; nt < 4; nt++) bh[nt] = __ldg(&g_w1f[fb + nt * 32]);
            // A fragments: pre-converted tf32 bits straight from smem
            int rb = r0 * HS_STRIDE + k8 * 8 + t;
            uint32_t a[4];
            a[0] = Hs[rb];
            a[1] = Hs[rb + 8 * HS_STRIDE];
            a[2] = Hs[rb + 4];
            a[3] = Hs[rb + 8 * HS_STRIDE + 4];
#pragma unroll
            for (int nt = 0; nt < 4; nt++) {
                uint32_t bv[2] = {bh[nt].x, bh[nt].y};
                mma_tf32(acc[nt], a, bv);
            }
        }

        // ---- epilogue for this n-group (u in [8*ng, 8*ng+8)) ----
        float efl[4], efh[4];
#pragma unroll
        for (int nt = 0; nt < 4; nt++) {
            float* c = acc[nt];
            float pl = ear[0][vb] * c[0] + ear[0][vb + 1] * c[1];
            float ph = ear[1][vb] * c[2] + ear[1][vb + 1] * c[3];
            pl += __shfl_xor_sync(0xffffffffu, pl, 1);
            ph += __shfl_xor_sync(0xffffffffu, ph, 1);
            int u = 8 * ng + 2 * nt + (t >> 1);
            float el = xs[r0 * XS_STRIDE + u] * pl * 0.0625f;
            float eh = xs[r1 * XS_STRIDE + u] * ph * 0.0625f;
            efl[nt] = el; efh[nt] = eh;
            // r accumulation (t-pairs duplicate; corrected by 0.5 at the end)
            const float4* sp = (const float4*)&sces[u * 16];
            float4 s0 = sp[0], s1 = sp[1], s2 = sp[2], s3 = sp[3];
            racc[0][0] += el * (ear[0][0] * s0.x + ear[0][1] * s1.x + ear[0][2] * s2.x + ear[0][3] * s3.x);
            racc[0][1] += el * (ear[0][0] * s0.y + ear[0][1] * s1.y + ear[0][2] * s2.y + ear[0][3] * s3.y);
            racc[0][2] += el * (ear[0][0] * s0.z + ear[0][1] * s1.z + ear[0][2] * s2.z + ear[0][3] * s3.z);
            racc[0][3] += el * (ear[0][0] * s0.w + ear[0][1] * s1.w + ear[0][2] * s2.w + ear[0][3] * s3.w);
            racc[1][0] += eh * (ear[1][0] * s0.x + ear[1][1] * s1.x + ear[1][2] * s2.x + ear[1][3] * s3.x);
            racc[1][1] += eh * (ear[1][0] * s0.y + ear[1][1] * s1.y + ear[1][2] * s2.y + ear[1][3] * s3.y);
            racc[1][2] += eh * (ear[1][0] * s0.z + ear[1][1] * s1.z + ear[1][2] * s2.z + ear[1][3] * s3.z);
            racc[1][3] += eh * (ear[1][0] * s0.w + ear[1][1] * s1.w + ear[1][2] * s2.w + ear[1][3] * s3.w);
        }
        // regroup u's for v4 RED: t0 -> u{0..3}+8ng, t2 -> u{4..7}+8ng
        float xl[4], xh[4];
#pragma unroll
        for (int nt = 0; nt < 4; nt++) {
            xl[nt] = __shfl_xor_sync(0xffffffffu, efl[nt], 2);
            xh[nt] = __shfl_xor_sync(0xffffffffu, efh[nt], 2);
        }
        if ((t & 1) == 0) {
            int ubase = 8 * ng + ((t == 0) ? 0 : 4);
            float a0, a1, a2, a3, b0, b1, b2, b3;
            if (t == 0) {
                a0 = efl[0]; a1 = xl[0]; a2 = efl[1]; a3 = xl[1];
                b0 = efh[0]; b1 = xh[0]; b2 = efh[1]; b3 = xh[1];
            } else {
                a0 = xl[2]; a1 = efl[2]; a2 = xl[3]; a3 = efl[3];
                b0 = xh[2]; b1 = efh[2]; b2 = xh[3]; b3 = efh[3];
            }
            const float sn = 0.25f;  // segment norm 1/sqrt(16)
            red_add_v4(&g_agg[(size_t)d0 * MUL + ubase], a0 * sn, a1 * sn, a2 * sn, a3 * sn);
            red_add_v4(&g_agg[(size_t)d1 * MUL + ubase], b0 * sn, b1 * sn, b2 * sn, b3 * sn);
        }
    }

    // ---- finalize edge_out: reduce racc over the 4 lanes of the group ----
#pragma unroll
    for (int i = 0; i < 2; i++)
#pragma unroll
        for (int v = 0; v < 4; v++) {
            float val = racc[i][v];
            val += __shfl_xor_sync(0xffffffffu, val, 1);
            val += __shfl_xor_sync(0xffffffffu, val, 2);
            racc[i][v] = val;
        }
    const float C2 = 0.5f * 0.022097086912079608f;  // 0.5 dup-fix * 1/(4*sqrt(128))
    if (t == 0) {
        size_t el = (size_t)(blockIdx.x * 128 + r0);
        size_t eh = (size_t)(blockIdx.x * 128 + r1);
        float4 ol = make_float4(ear[0][0] + racc[0][0] * C2,
                                ear[0][1] + racc[0][1] * C2,
                                ear[0][2] + racc[0][2] * C2,
                                ear[0][3] + racc[0][3] * C2);
        float4 oh = make_float4(ear[1][0] + racc[1][0] * C2,
                                ear[1][1] + racc[1][1] * C2,
                                ear[1][2] + racc[1][2] * C2,
                                ear[1][3] + racc[1][3] * C2);
        *(float4*)(ea_out + el * VE) = ol;
        *(float4*)(ea_out + eh * VE) = oh;
    }
}

// ---------------------------------------------------------------
extern "C" void kernel_launch(void* const* d_in, const int* in_sizes, int n_in,
                              void* d_out, int out_size)
{
    const float* node_features = (const float*)d_in[0];
    const float* node_attr     = (const float*)d_in[1];
    const int*   edge_src      = (const int*)d_in[2];
    const int*   edge_dst      = (const int*)d_in[3];
    const float* edge_attr     = (const float*)d_in[4];
    const float* edge_scalars  = (const float*)d_in[5];
    const float* sc_w    = (const float*)d_in[6];
    const float* lin1_w  = (const float*)d_in[7];
    const float* lin2_w  = (const float*)d_in[8];
    const float* alpha_w = (const float*)d_in[9];
    const float* sce_w   = (const float*)d_in[10];
    const float* fc_w0   = (const float*)d_in[11];
    const float* fc_w1   = (const float*)d_in[12];
    float* out = (float*)d_out;

    const int need_nf = NN * MUL;
    const int need_both = NN * MUL + NE * VE;
    float* nf_final = (out_size >= need_nf) ? out : nullptr;
    float* ea_final = (out_size >= need_both) ? (out + (size_t)NN * MUL) : nullptr;

    cudaFuncSetAttribute(edge_mma_kernel,
                         cudaFuncAttributeMaxDynamicSharedMemorySize, SMEM_BYTES);

    const int node_grid = (NN + 255) / 256;
    const int edge_grid = NE / 128;   // 6250 blocks x 256 threads
    const int zero_grid = (NN * MUL + 255) / 256;
    const int frag_grid = (4 * 8 * 4 * 32 + 255) / 256;   // 16

    for (int l = 0; l < 2; l++) {
        const float* nf_in = (l == 0) ? node_features : nullptr;  // null -> g_nf
        const float* ea_in = (l == 0) ? edge_attr : nullptr;      // null -> g_ea
        float* ea_out = (l == 1) ? ea_final : nullptr;            // null -> g_ea
        float* nf_out = (l == 1) ? nf_final : nullptr;            // null -> g_nf

        w1_frag_kernel<<<frag_grid, 256>>>(fc_w1 + (size_t)l * FCH * W_NUMEL);
        fctp_dual_kernel<<<2 * node_grid, 256>>>(nf_in, node_attr,
                                                 sc_w + (size_t)l * MUL * AA * MUL,
                                                 lin1_w + (size_t)l * MUL * AA * MUL,
                                                 node_grid);
        zero_agg_kernel<<<zero_grid, 256>>>();
        edge_mma_kernel<<<edge_grid, 256, SMEM_BYTES>>>(
            edge_scalars, edge_src, edge_dst, ea_in, ea_out,
            fc_w0 + (size_t)l * FCI * FCH,
            sce_w + (size_t)l * MUL * VE * VE);
        node_post_kernel<<<node_grid, 256>>>(node_attr,
                                             lin2_w + (size_t)l * MUL * AA * MUL,
                                             alpha_w + (size_t)l * MUL * AA,
                                             nf_out, (l == 0) ? 1 : 0);
    }
}

// round 15
// speedup vs baseline: 2.1634x; 1.2097x over previous
#include <cuda_runtime.h>
#include <math.h>
#include <stdint.h>

#define NN 50000
#define NE 800000
#define MUL 32
#define AA 8
#define VE 4
#define FCI 16
#define FCH 64
#define W_NUMEL 128

// ---------- scratch (device-code-only symbols; never passed from host) ----------
__device__ __align__(16) float g_x[NN * MUL];     // lin1 output
__device__ __align__(16) float g_sc[NN * MUL];    // self-connection output
__device__ __align__(16) float g_agg[NN * MUL];   // scatter-add accumulator
__device__ __align__(16) float g_nf[NN * MUL];    // node features between layers
__device__ __align__(16) float g_ea[NE * VE];     // edge attrs between layers
// lane-major tf32 B-fragments of W1^T (edge GEMM): [(ng*8+k8)*4+nt][lane]
__device__ __align__(16) uint2 g_w1f[4 * 8 * 4 * 32];
// lane-major tf32 B-fragments for node fctp GEMM (sc|lin1, N=64): [kk*8+nt][lane]
__device__ __align__(16) uint2 g_fctpw[32 * 8 * 32];
// lane-major tf32 B-fragments for node post GEMM (lin2|alpha|pad, N=40): [kk*5+nt][lane]
__device__ __align__(16) uint2 g_npw[32 * 5 * 32];

// ---------------------------------------------------------------
__global__ void zero_agg_kernel() {
    int i = blockIdx.x * blockDim.x + threadIdx.x;
    if (i < NN * MUL / 4) ((float4*)g_agg)[i] = make_float4(0.f, 0.f, 0.f, 0.f);
}

// ---------------- MMA helpers ----------------
__device__ __forceinline__ uint32_t f2tf32(float f) {
    uint32_t r;
    asm("cvt.rna.tf32.f32 %0, %1;" : "=r"(r) : "f"(f));
    return r;
}
__device__ __forceinline__ void mma_tf32(float* c, const uint32_t* a, const uint32_t* b) {
    asm volatile(
        "mma.sync.aligned.m16n8k8.row.col.f32.tf32.tf32.f32 "
        "{%0,%1,%2,%3},{%4,%5,%6,%7},{%8,%9},{%0,%1,%2,%3};"
        : "+f"(c[0]), "+f"(c[1]), "+f"(c[2]), "+f"(c[3])
        : "r"(a[0]), "r"(a[1]), "r"(a[2]), "r"(a[3]), "r"(b[0]), "r"(b[1]));
}

// prep: lane-major tf32 B-fragments of W1^T (edge GEMM, single plane).
__global__ void w1_frag_kernel(const float* __restrict__ fw1) {
    int i = blockIdx.x * blockDim.x + threadIdx.x;   // 0 .. 4095
    if (i >= 4 * 8 * 4 * 32) return;
    int lane = i & 31, nt = (i >> 5) & 3, k8 = (i >> 7) & 7, ng = i >> 10;
    int g = lane >> 2, t = lane & 3;
    int n = 32 * ng + 8 * nt + g;
    int k = 8 * k8 + t;
    g_w1f[i] = make_uint2(f2tf32(fw1[k * W_NUMEL + n]),
                          f2tf32(fw1[(k + 4) * W_NUMEL + n]));
}

// prep: fctp GEMM B-fragments. K-dim = uv (256), k-step kk: (u=kk, v=t / t+4).
// n < 32 -> sc_w[u][v][n] ; n >= 32 -> lin1_w[u][v][n-32]. Layout [u][v][k]: u*256+v*32+k.
__global__ void fctpw_frag_kernel(const float* __restrict__ w_sc,
                                  const float* __restrict__ w_lin1) {
    int i = blockIdx.x * blockDim.x + threadIdx.x;   // 0 .. 8191
    if (i >= 32 * 8 * 32) return;
    int lane = i & 31, nt = (i >> 5) & 7, kk = i >> 8;
    int g = lane >> 2, t = lane & 3;
    const float* W = (nt < 4) ? w_sc : w_lin1;
    int n = 8 * (nt & 3) + g;
    g_fctpw[i] = make_uint2(f2tf32(W[kk * 256 + t * 32 + n]),
                            f2tf32(W[kk * 256 + (t + 4) * 32 + n]));
}

// prep: node-post GEMM B-fragments. nt 0..3 -> lin2_w ; nt 4 -> alpha (col 32, g==0 only).
__global__ void npw_frag_kernel(const float* __restrict__ lin2w,
                                const float* __restrict__ alw) {
    int i = blockIdx.x * blockDim.x + threadIdx.x;   // 0 .. 5119
    if (i >= 32 * 5 * 32) return;
    int lane = i & 31;
    int rem = i >> 5;
    int nt = rem % 5, kk = rem / 5;
    int g = lane >> 2, t = lane & 3;
    float b0 = 0.f, b1 = 0.f;
    if (nt < 4) {
        int n = 8 * nt + g;
        b0 = lin2w[kk * 256 + t * 32 + n];
        b1 = lin2w[kk * 256 + (t + 4) * 32 + n];
    } else if (g == 0) {
        b0 = alw[kk * 8 + t];
        b1 = alw[kk * 8 + t + 4];
    }
    g_npw[i] = make_uint2(f2tf32(b0), f2tf32(b1));
}

// ---------------------------------------------------------------
// fctp GEMM: C[node, 0:64] = outer(a,attr) @ [sc_w | lin1_w]. 128 nodes/block.
// A-fragment built on the fly: A[row][uv=8kk+t'] = a[row][kk] * attr[row][t'].
__global__ __launch_bounds__(256) void fctp_mma_kernel(
    const float* __restrict__ a, const float* __restrict__ battr)
{
    __shared__ float as_[128 * 40];   // 32 a + 8 attr per node
    int tid = threadIdx.x;
    int blockbase = blockIdx.x * 128;
    const float* ap = a ? a : g_nf;

    for (int q = tid; q < 1024; q += 256) {       // a rows: 128 x 8 float4
        int node = q >> 3, part = q & 7;
        int gn = blockbase + node;
        float4 v = make_float4(0.f, 0.f, 0.f, 0.f);
        if (gn < NN) v = ((const float4*)(ap + (size_t)gn * MUL))[part];
        *(float4*)&as_[node * 40 + part * 4] = v;
    }
    for (int q = tid; q < 256; q += 256) {        // attr: 128 x 2 float4
        int node = q >> 1, half = q & 1;
        int gn = blockbase + node;
        float4 v = make_float4(0.f, 0.f, 0.f, 0.f);
        if (gn < NN) v = ((const float4*)(battr + (size_t)gn * AA))[half];
        *(float4*)&as_[node * 40 + 32 + half * 4] = v;
    }
    __syncthreads();

    int lane = tid & 31, wp = tid >> 5, g = lane >> 2, t = lane & 3;
    int r0 = wp * 16 + g, r1 = r0 + 8;

    float at0 = as_[r0 * 40 + 32 + t], at0b = as_[r0 * 40 + 32 + t + 4];
    float at1 = as_[r1 * 40 + 32 + t], at1b = as_[r1 * 40 + 32 + t + 4];

    float acc[8][4];
#pragma unroll
    for (int nt = 0; nt < 8; nt++)
#pragma unroll
        for (int i = 0; i < 4; i++) acc[nt][i] = 0.f;

#pragma unroll 4
    for (int kk = 0; kk < 32; kk++) {
        float ar0 = as_[r0 * 40 + kk], ar1 = as_[r1 * 40 + kk];
        uint32_t afr[4];
        afr[0] = f2tf32(ar0 * at0);
        afr[1] = f2tf32(ar1 * at1);
        afr[2] = f2tf32(ar0 * at0b);
        afr[3] = f2tf32(ar1 * at1b);
        const uint2* wrow = g_fctpw + kk * 8 * 32 + lane;
#pragma unroll
        for (int nt = 0; nt < 8; nt++) {
            uint2 bb = __ldg(&wrow[nt * 32]);
            uint32_t bv[2] = {bb.x, bb.y};
            mma_tf32(acc[nt], afr, bv);
        }
    }

    const float s = 1.0f / 16.0f;
    int gn0 = blockbase + r0, gn1 = blockbase + r1;
#pragma unroll
    for (int nt = 0; nt < 8; nt++) {
        float* dst = (nt < 4) ? g_sc : g_x;
        int col = 8 * (nt & 3) + 2 * t;
        if (gn0 < NN)
            *(float2*)&dst[(size_t)gn0 * MUL + col] = make_float2(acc[nt][0] * s, acc[nt][1] * s);
        if (gn1 < NN)
            *(float2*)&dst[(size_t)gn1 * MUL + col] = make_float2(acc[nt][2] * s, acc[nt][3] * s);
    }
}

// node post GEMM: conv/alpha from outer(agg,attr) @ [lin2|alpha]; fused combine.
__global__ __launch_bounds__(256) void node_post_mma_kernel(
    const float* __restrict__ battr, float* __restrict__ out, int apply_sin)
{
    __shared__ float as_[128 * 40];
    int tid = threadIdx.x;
    int blockbase = blockIdx.x * 128;
    float* op = out ? out : g_nf;

    for (int q = tid; q < 1024; q += 256) {
        int node = q >> 3, part = q & 7;
        int gn = blockbase + node;
        float4 v = make_float4(0.f, 0.f, 0.f, 0.f);
        if (gn < NN) v = ((const float4*)(g_agg + (size_t)gn * MUL))[part];
        *(float4*)&as_[node * 40 + part * 4] = v;
    }
    for (int q = tid; q < 256; q += 256) {
        int node = q >> 1, half = q & 1;
        int gn = blockbase + node;
        float4 v = make_float4(0.f, 0.f, 0.f, 0.f);
        if (gn < NN) v = ((const float4*)(battr + (size_t)gn * AA))[half];
        *(float4*)&as_[node * 40 + 32 + half * 4] = v;
    }
    __syncthreads();

    int lane = tid & 31, wp = tid >> 5, g = lane >> 2, t = lane & 3;
    int r0 = wp * 16 + g, r1 = r0 + 8;

    float at0 = as_[r0 * 40 + 32 + t], at0b = as_[r0 * 40 + 32 + t + 4];
    float at1 = as_[r1 * 40 + 32 + t], at1b = as_[r1 * 40 + 32 + t + 4];

    float acc[5][4];
#pragma unroll
    for (int nt = 0; nt < 5; nt++)
#pragma unroll
        for (int i = 0; i < 4; i++) acc[nt][i] = 0.f;

#pragma unroll 4
    for (int kk = 0; kk < 32; kk++) {
        float ar0 = as_[r0 * 40 + kk], ar1 = as_[r1 * 40 + kk];
        uint32_t afr[4];
        afr[0] = f2tf32(ar0 * at0);
        afr[1] = f2tf32(ar1 * at1);
        afr[2] = f2tf32(ar0 * at0b);
        afr[3] = f2tf32(ar1 * at1b);
        const uint2* wrow = g_npw + kk * 5 * 32 + lane;
#pragma unroll
        for (int nt = 0; nt < 5; nt++) {
            uint2 bb = __ldg(&wrow[nt * 32]);
            uint32_t bv[2] = {bb.x, bb.y};
            mma_tf32(acc[nt], afr, bv);
        }
    }

    const float s = 1.0f / 16.0f;
    // alpha: col 32 lives in acc[4][0] (row r0) / acc[4][2] (row r1) of the t=0 lane.
    int src = (lane >> 2) << 2;
    float alpha0 = __shfl_sync(0xffffffffu, acc[4][0], src) * s;
    float alpha1 = __shfl_sync(0xffffffffu, acc[4][2], src) * s;

    int gn0 = blockbase + r0, gn1 = blockbase + r1;
#pragma unroll
    for (int nt = 0; nt < 4; nt++) {
        int col = 8 * nt + 2 * t;
        if (gn0 < NN) {
            float2 sc = *(const float2*)&g_sc[(size_t)gn0 * MUL + col];
            float o0 = sc.x + alpha0 * (acc[nt][0] * s);
            float o1 = sc.y + alpha0 * (acc[nt][1] * s);
            if (apply_sin) { o0 = sinf(o0); o1 = sinf(o1); }
            *(float2*)&op[(size_t)gn0 * MUL + col] = make_float2(o0, o1);
        }
        if (gn1 < NN) {
            float2 sc = *(const float2*)&g_sc[(size_t)gn1 * MUL + col];
            float o0 = sc.x + alpha1 * (acc[nt][2] * s);
            float o1 = sc.y + alpha1 * (acc[nt][3] * s);
            if (apply_sin) { o0 = sinf(o0); o1 = sinf(o1); }
            *(float2*)&op[(size_t)gn1 * MUL + col] = make_float2(o0, o1);
        }
    }
}

// 16B-aligned 4-wide global float add (native vector atomic on sm_90+).
__device__ __forceinline__ void red_add_v4(float* ptr, float a, float b, float c, float d)
{
#if defined(__CUDA_ARCH__) && (__CUDA_ARCH__ >= 900) && (CUDART_VERSION >= 12080)
    atomicAdd((float4*)ptr, make_float4(a, b, c, d));
#else
    atomicAdd(ptr + 0, a);
    atomicAdd(ptr + 1, b);
    atomicAdd(ptr + 2, c);
    atomicAdd(ptr + 3, d);
#endif
}

// smem layout (floats/words) for edge_mma_kernel
#define HS_STRIDE 68
#define XS_STRIDE 36
#define OFF_HS   0
#define OFF_XS   (128 * HS_STRIDE)                 // 8704
#define OFF_W0   (OFF_XS + 128 * XS_STRIDE)        // 13312
#define OFF_SCE  (OFF_W0 + FCI * FCH)              // 14336
#define OFF_EAS  (OFF_SCE + MUL * VE * VE)         // 14848
#define OFF_DSS  (OFF_EAS + 128 * 4)               // 15360
#define SMEM_FLOATS (OFF_DSS + 128)                // 15488
#define SMEM_BYTES (SMEM_FLOATS * 4)               // 61952

// Fused edge kernel (unchanged from round 14 best).
__global__ __launch_bounds__(256, 3) void edge_mma_kernel(
    const float* __restrict__ es, const int* __restrict__ src,
    const int* __restrict__ dst, const float* __restrict__ ea_in_p,
    float* __restrict__ ea_out_p, const float* __restrict__ fw0,
    const float* __restrict__ scew)
{
    extern __shared__ float sm[];
    uint32_t* Hs = (uint32_t*)(sm + OFF_HS);   // [128][68] tf32 bits of h
    float* xs   = sm + OFF_XS;    // [128][36] x[src[e]]
    float* w0s  = sm + OFF_W0;    // FC0 weights
    float* sces = sm + OFF_SCE;   // sce weights
    float* eas  = sm + OFF_EAS;   // [128][4] edge attrs
    int*   dss  = (int*)(sm + OFF_DSS);  // [128] dst

    int tid = threadIdx.x;
    for (int i = tid; i < FCI * FCH; i += 256) w0s[i] = fw0[i];
    for (int i = tid; i < MUL * VE * VE; i += 256) sces[i] = scew[i];
    __syncthreads();

    const float* ea_in = ea_in_p ? ea_in_p : g_ea;
    float* ea_out = ea_out_p ? ea_out_p : g_ea;

    // ---- h phase: 2 threads per edge, each computes 32 of the 64 h values ----
    {
        int e = tid & 127, jh = tid >> 7;
        int ge = blockIdx.x * 128 + e;
        float scl[FCI];
        const float4* esp = (const float4*)(es + (size_t)ge * FCI);
#pragma unroll
        for (int i = 0; i < 4; i++) {
            float4 tv = esp[i];
            scl[4 * i + 0] = tv.x; scl[4 * i + 1] = tv.y;
            scl[4 * i + 2] = tv.z; scl[4 * i + 3] = tv.w;
        }
        float h[32];
#pragma unroll
        for (int j = 0; j < 32; j++) h[j] = 0.0f;
#pragma unroll
        for (int i = 0; i < FCI; i++) {
            float si = scl[i];
            const float4* wr = (const float4*)&w0s[i * FCH + 32 * jh];
#pragma unroll
            for (int j4 = 0; j4 < 8; j4++) {
                float4 wv = wr[j4];
                h[4 * j4 + 0] += si * wv.x;
                h[4 * j4 + 1] += si * wv.y;
                h[4 * j4 + 2] += si * wv.z;
                h[4 * j4 + 3] += si * wv.w;
            }
        }
        uint4* hrow = (uint4*)(Hs + e * HS_STRIDE + 32 * jh);
#pragma unroll
        for (int q = 0; q < 8; q++) {
            uint4 pk;
            pk.x = f2tf32(__sinf(h[4 * q + 0] * 0.25f));
            pk.y = f2tf32(__sinf(h[4 * q + 1] * 0.25f));
            pk.z = f2tf32(__sinf(h[4 * q + 2] * 0.25f));
            pk.w = f2tf32(__sinf(h[4 * q + 3] * 0.25f));
            hrow[q] = pk;
        }
        if (jh == 0) {
            dss[e] = dst[ge];
            *(float4*)(eas + e * 4) = *(const float4*)(ea_in + (size_t)ge * VE);
            int sv = src[ge];
            const float4* xr = (const float4*)(g_x + (size_t)sv * MUL);
            float4* xd = (float4*)(xs + e * XS_STRIDE);
#pragma unroll
            for (int q = 0; q < 8; q++) xd[q] = xr[q];
        }
    }
    __syncthreads();

    // ---- MMA + epilogue: warp wp owns edges [16*wp, 16*wp+16) ----
    int lane = tid & 31, wp = tid >> 5, g = lane >> 2, t = lane & 3;
    int r0 = wp * 16 + g;
    int r1 = r0 + 8;

    float ear[2][4];
#pragma unroll
    for (int v = 0; v < 4; v++) {
        ear[0][v] = eas[r0 * 4 + v];
        ear[1][v] = eas[r1 * 4 + v];
    }
    int d0 = dss[r0], d1 = dss[r1];

    float racc[2][4];
#pragma unroll
    for (int i = 0; i < 2; i++)
#pragma unroll
        for (int v = 0; v < 4; v++) racc[i][v] = 0.f;

    int vb = (2 * t) & 3;

#pragma unroll 1
    for (int ng = 0; ng < 4; ng++) {
        float acc[4][4];
#pragma unroll
        for (int nt = 0; nt < 4; nt++)
#pragma unroll
            for (int i = 0; i < 4; i++) acc[nt][i] = 0.f;

#pragma unroll 1
        for (int k8 = 0; k8 < 8; k8++) {
            int fb = ((ng * 8 + k8) * 4) * 32 + lane;
            uint2 bh[4];
#pragma unroll
            for (int nt = 0; nt < 4; nt++) bh[nt] = __ldg(&g_w1f[fb + nt * 32]);
            int rb = r0 * HS_STRIDE + k8 * 8 + t;
            uint32_t a[4];
            a[0] = Hs[rb];
            a[1] = Hs[rb + 8 * HS_STRIDE];
            a[2] = Hs[rb + 4];
            a[3] = Hs[rb + 8 * HS_STRIDE + 4];
#pragma unroll
            for (int nt = 0; nt < 4; nt++) {
                uint32_t bv[2] = {bh[nt].x, bh[nt].y};
                mma_tf32(acc[nt], a, bv);
            }
        }

        float efl[4], efh[4];
#pragma unroll
        for (int nt = 0; nt < 4; nt++) {
            float* c = acc[nt];
            float pl = ear[0][vb] * c[0] + ear[0][vb + 1] * c[1];
            float ph = ear[1][vb] * c[2] + ear[1][vb + 1] * c[3];
            pl += __shfl_xor_sync(0xffffffffu, pl, 1);
            ph += __shfl_xor_sync(0xffffffffu, ph, 1);
            int u = 8 * ng + 2 * nt + (t >> 1);
            float el = xs[r0 * XS_STRIDE + u] * pl * 0.0625f;
            float eh = xs[r1 * XS_STRIDE + u] * ph * 0.0625f;
            efl[nt] = el; efh[nt] = eh;
            const float4* sp = (const float4*)&sces[u * 16];
            float4 s0 = sp[0], s1 = sp[1], s2 = sp[2], s3 = sp[3];
            racc[0][0] += el * (ear[0][0] * s0.x + ear[0][1] * s1.x + ear[0][2] * s2.x + ear[0][3] * s3.x);
            racc[0][1] += el * (ear[0][0] * s0.y + ear[0][1] * s1.y + ear[0][2] * s2.y + ear[0][3] * s3.y);
            racc[0][2] += el * (ear[0][0] * s0.z + ear[0][1] * s1.z + ear[0][2] * s2.z + ear[0][3] * s3.z);
            racc[0][3] += el * (ear[0][0] * s0.w + ear[0][1] * s1.w + ear[0][2] * s2.w + ear[0][3] * s3.w);
            racc[1][0] += eh * (ear[1][0] * s0.x + ear[1][1] * s1.x + ear[1][2] * s2.x + ear[1][3] * s3.x);
            racc[1][1] += eh * (ear[1][0] * s0.y + ear[1][1] * s1.y + ear[1][2] * s2.y + ear[1][3] * s3.y);
            racc[1][2] += eh * (ear[1][0] * s0.z + ear[1][1] * s1.z + ear[1][2] * s2.z + ear[1][3] * s3.z);
            racc[1][3] += eh * (ear[1][0] * s0.w + ear[1][1] * s1.w + ear[1][2] * s2.w + ear[1][3] * s3.w);
        }
        float xl[4], xh[4];
#pragma unroll
        for (int nt = 0; nt < 4; nt++) {
            xl[nt] = __shfl_xor_sync(0xffffffffu, efl[nt], 2);
            xh[nt] = __shfl_xor_sync(0xffffffffu, efh[nt], 2);
        }
        if ((t & 1) == 0) {
            int ubase = 8 * ng + ((t == 0) ? 0 : 4);
            float a0, a1, a2, a3, b0, b1, b2, b3;
            if (t == 0) {
                a0 = efl[0]; a1 = xl[0]; a2 = efl[1]; a3 = xl[1];
                b0 = efh[0]; b1 = xh[0]; b2 = efh[1]; b3 = xh[1];
            } else {
                a0 = xl[2]; a1 = efl[2]; a2 = xl[3]; a3 = efl[3];
                b0 = xh[2]; b1 = efh[2]; b2 = xh[3]; b3 = efh[3];
            }
            const float sn = 0.25f;
            red_add_v4(&g_agg[(size_t)d0 * MUL + ubase], a0 * sn, a1 * sn, a2 * sn, a3 * sn);
            red_add_v4(&g_agg[(size_t)d1 * MUL + ubase], b0 * sn, b1 * sn, b2 * sn, b3 * sn);
        }
    }

#pragma unroll
    for (int i = 0; i < 2; i++)
#pragma unroll
        for (int v = 0; v < 4; v++) {
            float val = racc[i][v];
            val += __shfl_xor_sync(0xffffffffu, val, 1);
            val += __shfl_xor_sync(0xffffffffu, val, 2);
            racc[i][v] = val;
        }
    const float C2 = 0.5f * 0.022097086912079608f;
    if (t == 0) {
        size_t el = (size_t)(blockIdx.x * 128 + r0);
        size_t eh = (size_t)(blockIdx.x * 128 + r1);
        float4 ol = make_float4(ear[0][0] + racc[0][0] * C2,
                                ear[0][1] + racc[0][1] * C2,
                                ear[0][2] + racc[0][2] * C2,
                                ear[0][3] + racc[0][3] * C2);
        float4 oh = make_float4(ear[1][0] + racc[1][0] * C2,
                                ear[1][1] + racc[1][1] * C2,
                                ear[1][2] + racc[1][2] * C2,
                                ear[1][3] + racc[1][3] * C2);
        *(float4*)(ea_out + el * VE) = ol;
        *(float4*)(ea_out + eh * VE) = oh;
    }
}

// ---------------------------------------------------------------
extern "C" void kernel_launch(void* const* d_in, const int* in_sizes, int n_in,
                              void* d_out, int out_size)
{
    const float* node_features = (const float*)d_in[0];
    const float* node_attr     = (const float*)d_in[1];
    const int*   edge_src      = (const int*)d_in[2];
    const int*   edge_dst      = (const int*)d_in[3];
    const float* edge_attr     = (const float*)d_in[4];
    const float* edge_scalars  = (const float*)d_in[5];
    const float* sc_w    = (const float*)d_in[6];
    const float* lin1_w  = (const float*)d_in[7];
    const float* lin2_w  = (const float*)d_in[8];
    const float* alpha_w = (const float*)d_in[9];
    const float* sce_w   = (const float*)d_in[10];
    const float* fc_w0   = (const float*)d_in[11];
    const float* fc_w1   = (const float*)d_in[12];
    float* out = (float*)d_out;

    const int need_nf = NN * MUL;
    const int need_both = NN * MUL + NE * VE;
    float* nf_final = (out_size >= need_nf) ? out : nullptr;
    float* ea_final = (out_size >= need_both) ? (out + (size_t)NN * MUL) : nullptr;

    cudaFuncSetAttribute(edge_mma_kernel,
                         cudaFuncAttributeMaxDynamicSharedMemorySize, SMEM_BYTES);

    const int node_mma_grid = (NN + 127) / 128;   // 391
    const int edge_grid = NE / 128;               // 6250
    const int zero_grid = (NN * MUL / 4 + 255) / 256;

    for (int l = 0; l < 2; l++) {
        const float* nf_in = (l == 0) ? node_features : nullptr;  // null -> g_nf
        const float* ea_in = (l == 0) ? edge_attr : nullptr;      // null -> g_ea
        float* ea_out = (l == 1) ? ea_final : nullptr;            // null -> g_ea
        float* nf_out = (l == 1) ? nf_final : nullptr;            // null -> g_nf

        w1_frag_kernel<<<16, 256>>>(fc_w1 + (size_t)l * FCH * W_NUMEL);
        fctpw_frag_kernel<<<32, 256>>>(sc_w + (size_t)l * MUL * AA * MUL,
                                       lin1_w + (size_t)l * MUL * AA * MUL);
        npw_frag_kernel<<<20, 256>>>(lin2_w + (size_t)l * MUL * AA * MUL,
                                     alpha_w + (size_t)l * MUL * AA);
        fctp_mma_kernel<<<node_mma_grid, 256>>>(nf_in, node_attr);
        zero_agg_kernel<<<zero_grid, 256>>>();
        edge_mma_kernel<<<edge_grid, 256, SMEM_BYTES>>>(
            edge_scalars, edge_src, edge_dst, ea_in, ea_out,
            fc_w0 + (size_t)l * FCI * FCH,
            sce_w + (size_t)l * MUL * VE * VE);
        node_post_mma_kernel<<<node_mma_grid, 256>>>(node_attr, nf_out, (l == 0) ? 1 : 0);
    }
}